// round 2
// baseline (speedup 1.0000x reference)
#include <cuda_runtime.h>
#include <math.h>

#define NPIX 3136   // 56*56
#define CCH  256
#define HID  1024

// ---------------- scratch (allocation-free: __device__ globals, referenced directly) ----------------
__device__ float g_t1 [NPIX*CCH];   // LN1 out, [N,C]
__device__ float g_qkv[NPIX*768];   // [N, 3C]
__device__ float g_ao [NPIX*CCH];   // attention out, [N,C]
__device__ float g_pr [NPIX*CCH];   // proj out, [N,C]
__device__ float g_x1 [NPIX*CCH];   // residual1, [N,C]
__device__ float g_t2 [NPIX*CCH];   // LN2 out, [N,C]
__device__ float g_h  [NPIX*HID];   // fc1 out, [N,HID]
__device__ float g_f2 [NPIX*CCH];   // fc2 out, [N,C]

// ---------------- channel LayerNorm (+optional residual add) ----------------
// x: [C, N] channel-major. ADD: if true, y = x + g_pr and also writes g_x1 = y.
// Writes t = LN_c(y)*w+b as [N, C].
template <bool ADD>
__global__ void ln_kernel(const float* __restrict__ x,
                          const float* __restrict__ w, const float* __restrict__ b,
                          float* __restrict__ t)
{
    __shared__ float s[CCH][33];
    __shared__ float rsum[8][32], rsum2[8][32];
    __shared__ float mu_s[32], rs_s[32];
    const int tid  = threadIdx.x;
    const int lane = tid & 31, wp = tid >> 5;
    const int p0   = blockIdx.x * 32;

    if (ADD) {
        const int cl = tid & 31, pl8 = tid >> 5;
        #pragma unroll
        for (int pp = 0; pp < 4; pp++) {
            const int pl = pp*8 + pl8;
            #pragma unroll
            for (int cc = 0; cc < 8; cc++) {
                const int c = cc*32 + cl;
                s[c][pl] = g_pr[(p0+pl)*CCH + c];
            }
        }
        __syncthreads();
    }
    float sum = 0.f, sum2 = 0.f;
    #pragma unroll
    for (int k = 0; k < 32; k++) {
        const int c = wp*32 + k;
        float v = x[c*NPIX + p0 + lane];
        if (ADD) v += s[c][lane];
        s[c][lane] = v;
        sum += v; sum2 += v*v;
    }
    rsum[wp][lane] = sum; rsum2[wp][lane] = sum2;
    __syncthreads();
    if (tid < 32) {
        float a = 0.f, a2 = 0.f;
        #pragma unroll
        for (int k = 0; k < 8; k++) { a += rsum[k][tid]; a2 += rsum2[k][tid]; }
        const float mu  = a * (1.f/CCH);
        const float var = a2 * (1.f/CCH) - mu*mu;
        mu_s[tid] = mu; rs_s[tid] = rsqrtf(var + 1e-5f);
    }
    __syncthreads();
    {
        const int cl = tid & 31, pl8 = tid >> 5;
        #pragma unroll
        for (int pp = 0; pp < 4; pp++) {
            const int pl = pp*8 + pl8;
            const float mu = mu_s[pl], rs = rs_s[pl];
            #pragma unroll
            for (int cc = 0; cc < 8; cc++) {
                const int c = cc*32 + cl;
                const float y = s[c][pl];
                if (ADD) g_x1[(p0+pl)*CCH + c] = y;
                t[(p0+pl)*CCH + c] = (y - mu)*rs*w[c] + b[c];
            }
        }
    }
}

// ---------------- generic GEMM: C[m,n] = act( sum_k A[m,k]*B[n,k] + bias[n] ) ----------------
// A: [M,K] row-major, B: [N,K] row-major. act: 0=none, 1=exact GELU.
// Tiles: 64x64x16, 256 threads, 4x4 per thread. Requires M%64==N%64==K%16==0.
__global__ void gemm_nt(const float* __restrict__ A, const float* __restrict__ B,
                        const float* __restrict__ bias, float* __restrict__ C,
                        int M, int N, int K, int act)
{
    __shared__ float As[16][68];
    __shared__ float Bs[16][68];
    const int tid = threadIdx.x;
    const int tx = tid & 15, ty = tid >> 4;
    const int bm = blockIdx.y * 64, bn = blockIdx.x * 64;
    const int lr = tid >> 2;        // 0..63 (row within tile)
    const int lk = (tid & 3) * 4;   // 0,4,8,12

    float acc[4][4] = {};
    for (int k0 = 0; k0 < K; k0 += 16) {
        const float4 av = *(const float4*)&A[(bm+lr)*K + k0 + lk];
        const float4 bv = *(const float4*)&B[(bn+lr)*K + k0 + lk];
        As[lk+0][lr] = av.x; As[lk+1][lr] = av.y; As[lk+2][lr] = av.z; As[lk+3][lr] = av.w;
        Bs[lk+0][lr] = bv.x; Bs[lk+1][lr] = bv.y; Bs[lk+2][lr] = bv.z; Bs[lk+3][lr] = bv.w;
        __syncthreads();
        #pragma unroll
        for (int kk = 0; kk < 16; kk++) {
            const float4 a4 = *(const float4*)&As[kk][ty*4];
            const float4 b4 = *(const float4*)&Bs[kk][tx*4];
            const float a[4] = {a4.x, a4.y, a4.z, a4.w};
            const float bb[4] = {b4.x, b4.y, b4.z, b4.w};
            #pragma unroll
            for (int i = 0; i < 4; i++)
                #pragma unroll
                for (int j = 0; j < 4; j++)
                    acc[i][j] += a[i]*bb[j];
        }
        __syncthreads();
    }
    #pragma unroll
    for (int i = 0; i < 4; i++) {
        const int m = bm + ty*4 + i;
        float4 o;
        float v0 = acc[i][0] + bias[bn+tx*4+0];
        float v1 = acc[i][1] + bias[bn+tx*4+1];
        float v2 = acc[i][2] + bias[bn+tx*4+2];
        float v3 = acc[i][3] + bias[bn+tx*4+3];
        if (act == 1) {
            v0 = 0.5f*v0*(1.f + erff(v0*0.70710678118654752f));
            v1 = 0.5f*v1*(1.f + erff(v1*0.70710678118654752f));
            v2 = 0.5f*v2*(1.f + erff(v2*0.70710678118654752f));
            v3 = 0.5f*v3*(1.f + erff(v3*0.70710678118654752f));
        }
        o.x = v0; o.y = v1; o.z = v2; o.w = v3;
        *(float4*)&C[m*N + bn + tx*4] = o;
    }
}

// ---------------- local window attention ----------------
// one block per pixel, one warp per head. reads g_qkv, writes g_ao.
__global__ void attn_kernel()
{
    const int n = blockIdx.x;
    const int h = threadIdx.x >> 5, lane = threadIdx.x & 31;
    const int i = n / 56, j = n % 56;
    const unsigned FULL = 0xffffffffu;

    const float q = g_qkv[n*768 + h*32 + lane];
    const int i0 = max(i-3, 0), i1 = min(i+3, 55);
    const int j0 = max(j-3, 0), j1 = min(j+3, 55);

    float sc0 = -3.0e38f, sc1 = -3.0e38f;
    int t = 0;
    for (int ii = i0; ii <= i1; ii++)
        for (int jj = j0; jj <= j1; jj++) {
            const int m = ii*56 + jj;
            float s = q * g_qkv[m*768 + 256 + h*32 + lane];
            #pragma unroll
            for (int o = 16; o; o >>= 1) s += __shfl_xor_sync(FULL, s, o);
            s *= 0.17677669529663687f;   // 1/sqrt(32)
            if (t < 32) { if (lane == t)      sc0 = s; }
            else        { if (lane == t - 32) sc1 = s; }
            t++;
        }
    float mx = fmaxf(sc0, sc1);
    #pragma unroll
    for (int o = 16; o; o >>= 1) mx = fmaxf(mx, __shfl_xor_sync(FULL, mx, o));
    const float e0 = expf(sc0 - mx);   // masked/invalid slots underflow to 0
    const float e1 = expf(sc1 - mx);
    float sm = e0 + e1;
    #pragma unroll
    for (int o = 16; o; o >>= 1) sm += __shfl_xor_sync(FULL, sm, o);
    const float inv = 1.f / sm;

    float acc = 0.f;
    t = 0;
    for (int ii = i0; ii <= i1; ii++)
        for (int jj = j0; jj <= j1; jj++) {
            const int m = ii*56 + jj;
            const float v = g_qkv[m*768 + 512 + h*32 + lane];
            const float p = __shfl_sync(FULL, (t < 32) ? e0 : e1, t & 31);
            acc += p * v;
            t++;
        }
    g_ao[n*CCH + h*32 + lane] = acc * inv;
}

// ---------------- final: out[c, n] = g_x1[n,c] + g_f2[n,c] (transpose-add) ----------------
__global__ void add_t_kernel(float* __restrict__ out)
{
    __shared__ float s[32][33];
    const int tx = threadIdx.x, ty = threadIdx.y;    // 32 x 8
    const int n0 = blockIdx.x * 32, c0 = blockIdx.y * 32;
    #pragma unroll
    for (int r = 0; r < 4; r++) {
        const int nl = ty + 8*r;
        const int idx = (n0+nl)*CCH + c0 + tx;
        s[tx][nl] = g_x1[idx] + g_f2[idx];
    }
    __syncthreads();
    #pragma unroll
    for (int r = 0; r < 4; r++) {
        const int cl = ty + 8*r;
        out[(c0+cl)*NPIX + n0 + tx] = s[cl][tx];
    }
}

// ---------------- device-global pointer helpers (compile-time symbol refs in kernels) ----------------
__global__ void noop() {}

extern "C" void kernel_launch(void* const* d_in, const int* in_sizes, int n_in,
                              void* d_out, int out_size)
{
    const float* x       = (const float*)d_in[0];
    const float* norm1_w = (const float*)d_in[1];
    const float* norm1_b = (const float*)d_in[2];
    const float* qkv_w   = (const float*)d_in[3];
    const float* qkv_b   = (const float*)d_in[4];
    const float* proj_w  = (const float*)d_in[5];
    const float* proj_b  = (const float*)d_in[6];
    const float* norm2_w = (const float*)d_in[7];
    const float* norm2_b = (const float*)d_in[8];
    const float* fc1_w   = (const float*)d_in[9];
    const float* fc1_b   = (const float*)d_in[10];
    const float* fc2_w   = (const float*)d_in[11];
    const float* fc2_b   = (const float*)d_in[12];
    float* out = (float*)d_out;

    // device-global scratch addresses: taken once via static init of device pointers
    // (kernels that read/write the globals reference them directly; gemm kernels
    //  receive them as arguments — the addresses below are resolved host-side
    //  without any CUDA API calls by using the fact that gemm args come from
    //  kernels' own symbol space via small wrapper launches is NOT possible, so
    //  we pass via cudaGetSymbolAddress-free route: static device pointers.)
    static float *t1 = nullptr, *qkv = nullptr, *t2 = nullptr, *hbuf = nullptr, *f2 = nullptr, *ao = nullptr;
    if (!t1) {
        cudaGetSymbolAddress((void**)&t1,   g_t1);
        cudaGetSymbolAddress((void**)&qkv,  g_qkv);
        cudaGetSymbolAddress((void**)&ao,   g_ao);
        cudaGetSymbolAddress((void**)&t2,   g_t2);
        cudaGetSymbolAddress((void**)&hbuf, g_h);
        cudaGetSymbolAddress((void**)&f2,   g_f2);
    }
    float* pr; cudaGetSymbolAddress((void**)&pr, g_pr);  // cheap query, capture-safe

    // 1. LN1: t1 = LN(x)
    ln_kernel<false><<<NPIX/32, 256>>>(x, norm1_w, norm1_b, t1);
    // 2. QKV: qkv = t1 @ qkv_w^T + b     [3136,768]
    gemm_nt<<<dim3(768/64, NPIX/64), 256>>>(t1, qkv_w, qkv_b, qkv, NPIX, 768, CCH, 0);
    // 3. local attention -> g_ao [3136,256]
    attn_kernel<<<NPIX, 256>>>();
    // 4. proj: pr = ao @ proj_w^T + b
    gemm_nt<<<dim3(CCH/64, NPIX/64), 256>>>(ao, proj_w, proj_b, pr, NPIX, CCH, CCH, 0);
    // 5. x1 = x + pr ; t2 = LN(x1)   (reads g_pr, writes g_x1 internally)
    ln_kernel<true><<<NPIX/32, 256>>>(x, norm2_w, norm2_b, t2);
    // 6. fc1 + GELU: h = gelu(t2 @ fc1_w^T + b)  [3136,1024]
    gemm_nt<<<dim3(HID/64, NPIX/64), 256>>>(t2, fc1_w, fc1_b, hbuf, NPIX, HID, CCH, 1);
    // 7. fc2: f2 = h @ fc2_w^T + b
    gemm_nt<<<dim3(CCH/64, NPIX/64), 256>>>(hbuf, fc2_w, fc2_b, f2, NPIX, CCH, HID, 0);
    // 8. out[c,n] = x1[n,c] + f2[n,c]
    add_t_kernel<<<dim3(NPIX/32, CCH/32), dim3(32, 8)>>>(out);
}

// round 4
// speedup vs baseline: 1.8738x; 1.8738x over previous
#include <cuda_runtime.h>
#include <math.h>

#define NPIX 3136   // 56*56
#define CCH  256
#define HID  1024

// ---------------- scratch (allocation-free: __device__ globals) ----------------
__device__ float g_t1 [NPIX*CCH];   // LN1 out, [N,C]
__device__ float g_qkv[NPIX*768];   // [N, 3C]
__device__ float g_ao [NPIX*CCH];   // attention out, [N,C]
__device__ float g_pr [NPIX*CCH];   // proj out, [N,C]
__device__ float g_x1 [NPIX*CCH];   // residual1, [N,C]
__device__ float g_t2 [NPIX*CCH];   // LN2 out, [N,C]
__device__ float g_h  [NPIX*HID];   // fc1 out, [N,HID]
__device__ float g_f2 [NPIX*CCH];   // fc2 out, [N,C]

// ---------------- channel LayerNorm (+optional residual add) ----------------
template <bool ADD>
__global__ void ln_kernel(const float* __restrict__ x,
                          const float* __restrict__ w, const float* __restrict__ b,
                          float* __restrict__ t)
{
    __shared__ float s[CCH][33];
    __shared__ float rsum[8][32], rsum2[8][32];
    __shared__ float mu_s[32], rs_s[32];
    const int tid  = threadIdx.x;
    const int lane = tid & 31, wp = tid >> 5;
    const int p0   = blockIdx.x * 32;

    if (ADD) {
        const int cl = tid & 31, pl8 = tid >> 5;
        #pragma unroll
        for (int pp = 0; pp < 4; pp++) {
            const int pl = pp*8 + pl8;
            #pragma unroll
            for (int cc = 0; cc < 8; cc++) {
                const int c = cc*32 + cl;
                s[c][pl] = g_pr[(p0+pl)*CCH + c];
            }
        }
        __syncthreads();
    }
    float sum = 0.f, sum2 = 0.f;
    #pragma unroll
    for (int k = 0; k < 32; k++) {
        const int c = wp*32 + k;
        float v = x[c*NPIX + p0 + lane];
        if (ADD) v += s[c][lane];
        s[c][lane] = v;
        sum += v; sum2 += v*v;
    }
    rsum[wp][lane] = sum; rsum2[wp][lane] = sum2;
    __syncthreads();
    if (tid < 32) {
        float a = 0.f, a2 = 0.f;
        #pragma unroll
        for (int k = 0; k < 8; k++) { a += rsum[k][tid]; a2 += rsum2[k][tid]; }
        const float mu  = a * (1.f/CCH);
        const float var = a2 * (1.f/CCH) - mu*mu;
        mu_s[tid] = mu; rs_s[tid] = rsqrtf(var + 1e-5f);
    }
    __syncthreads();
    {
        const int cl = tid & 31, pl8 = tid >> 5;
        #pragma unroll
        for (int pp = 0; pp < 4; pp++) {
            const int pl = pp*8 + pl8;
            const float mu = mu_s[pl], rs = rs_s[pl];
            #pragma unroll
            for (int cc = 0; cc < 8; cc++) {
                const int c = cc*32 + cl;
                const float y = s[c][pl];
                if (ADD) g_x1[(p0+pl)*CCH + c] = y;
                t[(p0+pl)*CCH + c] = (y - mu)*rs*w[c] + b[c];
            }
        }
    }
}

// ---------------- generic GEMM (unchanged, known-good) ----------------
__global__ void gemm_nt(const float* __restrict__ A, const float* __restrict__ B,
                        const float* __restrict__ bias, float* __restrict__ C,
                        int M, int N, int K, int act)
{
    __shared__ float As[16][68];
    __shared__ float Bs[16][68];
    const int tid = threadIdx.x;
    const int tx = tid & 15, ty = tid >> 4;
    const int bm = blockIdx.y * 64, bn = blockIdx.x * 64;
    const int lr = tid >> 2;
    const int lk = (tid & 3) * 4;

    float acc[4][4] = {};
    for (int k0 = 0; k0 < K; k0 += 16) {
        const float4 av = *(const float4*)&A[(bm+lr)*K + k0 + lk];
        const float4 bv = *(const float4*)&B[(bn+lr)*K + k0 + lk];
        As[lk+0][lr] = av.x; As[lk+1][lr] = av.y; As[lk+2][lr] = av.z; As[lk+3][lr] = av.w;
        Bs[lk+0][lr] = bv.x; Bs[lk+1][lr] = bv.y; Bs[lk+2][lr] = bv.z; Bs[lk+3][lr] = bv.w;
        __syncthreads();
        #pragma unroll
        for (int kk = 0; kk < 16; kk++) {
            const float4 a4 = *(const float4*)&As[kk][ty*4];
            const float4 b4 = *(const float4*)&Bs[kk][tx*4];
            const float a[4] = {a4.x, a4.y, a4.z, a4.w};
            const float bb[4] = {b4.x, b4.y, b4.z, b4.w};
            #pragma unroll
            for (int i = 0; i < 4; i++)
                #pragma unroll
                for (int j = 0; j < 4; j++)
                    acc[i][j] += a[i]*bb[j];
        }
        __syncthreads();
    }
    #pragma unroll
    for (int i = 0; i < 4; i++) {
        const int m = bm + ty*4 + i;
        float4 o;
        float v0 = acc[i][0] + bias[bn+tx*4+0];
        float v1 = acc[i][1] + bias[bn+tx*4+1];
        float v2 = acc[i][2] + bias[bn+tx*4+2];
        float v3 = acc[i][3] + bias[bn+tx*4+3];
        if (act == 1) {
            v0 = 0.5f*v0*(1.f + erff(v0*0.70710678118654752f));
            v1 = 0.5f*v1*(1.f + erff(v1*0.70710678118654752f));
            v2 = 0.5f*v2*(1.f + erff(v2*0.70710678118654752f));
            v3 = 0.5f*v3*(1.f + erff(v3*0.70710678118654752f));
        }
        o.x = v0; o.y = v1; o.z = v2; o.w = v3;
        *(float4*)&C[m*N + bn + tx*4] = o;
    }
}

// ---------------- local window attention (tiled, smem, shuffle-free inner loops) ----------------
// grid (7,7,8): 8x8 query tile x head. block 256 threads.
// thread = (q 0..63, qu 0..3). Phase1: q-vector in regs, full 32-dim dots for
// neighbors s = qu+4j. Phase2: 4-lane softmax. Phase3: thread owns dims qu*8..+8.
__global__ void attn_kernel()
{
    __shared__ float Ks[196][36];   // 14x14 halo, stride 36 for lds.128 bank spread
    __shared__ float Vs[196][36];
    __shared__ float Ps[64][56];    // normalized probs
    const int tid = threadIdx.x;
    const int h  = blockIdx.z;
    const int ti = blockIdx.y, tj = blockIdx.x;
    const int gi0 = ti*8 - 3, gj0 = tj*8 - 3;

    // stage K,V halo (OOB -> 0; masked later anyway)
    for (int idx = tid; idx < 196*32; idx += 256) {
        const int pix = idx >> 5, d = idx & 31;
        const int pi = pix / 14, pj = pix - pi*14;
        const int ai = gi0 + pi, aj = gj0 + pj;
        float kv = 0.f, vv = 0.f;
        if (ai >= 0 && ai < 56 && aj >= 0 && aj < 56) {
            const int m = ai*56 + aj;
            kv = g_qkv[m*768 + 256 + h*32 + d];
            vv = g_qkv[m*768 + 512 + h*32 + d];
        }
        Ks[pix][d] = kv;
        Vs[pix][d] = vv;
    }
    __syncthreads();

    const int q  = tid >> 2, qu = tid & 3;
    const int qi = q >> 3,  qj = q & 7;
    const int gqi = ti*8 + qi, gqj = tj*8 + qj;
    const int n = gqi*56 + gqj;

    // full q vector in registers
    float qv[32];
    {
        const float4* qp = (const float4*)&g_qkv[n*768 + h*32];
        #pragma unroll
        for (int k = 0; k < 8; k++) {
            const float4 v = qp[k];
            qv[4*k+0] = v.x; qv[4*k+1] = v.y; qv[4*k+2] = v.z; qv[4*k+3] = v.w;
        }
    }

    // scores for s = qu + 4j
    float sc[13];
    #pragma unroll
    for (int j = 0; j < 13; j++) sc[j] = -3.0e38f;
    #pragma unroll
    for (int j = 0; j < 13; j++) {
        const int s = qu + 4*j;
        if (s < 49) {
            const int dy = s / 7 - 3, dx = s - (s/7)*7 - 3;
            const int ai = gqi + dy, aj = gqj + dx;
            if (ai >= 0 && ai < 56 && aj >= 0 && aj < 56) {
                const int nb = (qi + dy + 3)*14 + (qj + dx + 3);
                const float4* kp = (const float4*)&Ks[nb][0];
                float acc = 0.f;
                #pragma unroll
                for (int k = 0; k < 8; k++) {
                    const float4 kv = kp[k];
                    acc += qv[4*k+0]*kv.x + qv[4*k+1]*kv.y
                         + qv[4*k+2]*kv.z + qv[4*k+3]*kv.w;
                }
                sc[j] = acc * 0.17677669529663687f;  // 1/sqrt(32)
            }
        }
    }

    // softmax across the 4 lanes of this query (lanes q*4..q*4+3 are contiguous)
    const unsigned FULL = 0xffffffffu;
    float mx = sc[0];
    #pragma unroll
    for (int j = 1; j < 13; j++) mx = fmaxf(mx, sc[j]);
    mx = fmaxf(mx, __shfl_xor_sync(FULL, mx, 1));
    mx = fmaxf(mx, __shfl_xor_sync(FULL, mx, 2));
    float lsum = 0.f;
    float pe[13];
    #pragma unroll
    for (int j = 0; j < 13; j++) { pe[j] = __expf(sc[j] - mx); lsum += pe[j]; }
    lsum += __shfl_xor_sync(FULL, lsum, 1);
    lsum += __shfl_xor_sync(FULL, lsum, 2);
    const float inv = 1.f / lsum;
    #pragma unroll
    for (int j = 0; j < 13; j++) {
        const int s = qu + 4*j;
        if (s < 49) Ps[q][s] = pe[j] * inv;
    }
    __syncthreads();

    // AV: thread owns dims d0 = qu*8 .. +8 of query q
    const int d0 = qu*8;
    float acc[8] = {};
    #pragma unroll
    for (int dy = -3; dy <= 3; dy++) {
        const int rowbase = (qi + dy + 3)*14 + (qj + 3);
        const int sbase = (dy+3)*7;
        #pragma unroll
        for (int dx = -3; dx <= 3; dx++) {
            const float p = Ps[q][sbase + dx + 3];
            const float4* vp = (const float4*)&Vs[rowbase + dx][d0];
            const float4 v0 = vp[0], v1 = vp[1];
            acc[0] += p*v0.x; acc[1] += p*v0.y; acc[2] += p*v0.z; acc[3] += p*v0.w;
            acc[4] += p*v1.x; acc[5] += p*v1.y; acc[6] += p*v1.z; acc[7] += p*v1.w;
        }
    }
    float4* op = (float4*)&g_ao[n*CCH + h*32 + d0];
    op[0] = make_float4(acc[0], acc[1], acc[2], acc[3]);
    op[1] = make_float4(acc[4], acc[5], acc[6], acc[7]);
}

// ---------------- final: out[c, n] = g_x1[n,c] + g_f2[n,c] ----------------
__global__ void add_t_kernel(float* __restrict__ out)
{
    __shared__ float s[32][33];
    const int tx = threadIdx.x, ty = threadIdx.y;    // 32 x 8
    const int n0 = blockIdx.x * 32, c0 = blockIdx.y * 32;
    #pragma unroll
    for (int r = 0; r < 4; r++) {
        const int nl = ty + 8*r;
        const int idx = (n0+nl)*CCH + c0 + tx;
        s[tx][nl] = g_x1[idx] + g_f2[idx];
    }
    __syncthreads();
    #pragma unroll
    for (int r = 0; r < 4; r++) {
        const int cl = ty + 8*r;
        out[(c0+cl)*NPIX + n0 + tx] = s[cl][tx];
    }
}

extern "C" void kernel_launch(void* const* d_in, const int* in_sizes, int n_in,
                              void* d_out, int out_size)
{
    const float* x       = (const float*)d_in[0];
    const float* norm1_w = (const float*)d_in[1];
    const float* norm1_b = (const float*)d_in[2];
    const float* qkv_w   = (const float*)d_in[3];
    const float* qkv_b   = (const float*)d_in[4];
    const float* proj_w  = (const float*)d_in[5];
    const float* proj_b  = (const float*)d_in[6];
    const float* norm2_w = (const float*)d_in[7];
    const float* norm2_b = (const float*)d_in[8];
    const float* fc1_w   = (const float*)d_in[9];
    const float* fc1_b   = (const float*)d_in[10];
    const float* fc2_w   = (const float*)d_in[11];
    const float* fc2_b   = (const float*)d_in[12];
    float* out = (float*)d_out;

    static float *t1 = nullptr, *qkv = nullptr, *t2 = nullptr, *hbuf = nullptr,
                 *f2 = nullptr, *ao = nullptr, *pr = nullptr;
    if (!t1) {
        cudaGetSymbolAddress((void**)&t1,   g_t1);
        cudaGetSymbolAddress((void**)&qkv,  g_qkv);
        cudaGetSymbolAddress((void**)&ao,   g_ao);
        cudaGetSymbolAddress((void**)&t2,   g_t2);
        cudaGetSymbolAddress((void**)&hbuf, g_h);
        cudaGetSymbolAddress((void**)&f2,   g_f2);
        cudaGetSymbolAddress((void**)&pr,   g_pr);
    }

    // 1. LN1
    ln_kernel<false><<<NPIX/32, 256>>>(x, norm1_w, norm1_b, t1);
    // 2. QKV
    gemm_nt<<<dim3(768/64, NPIX/64), 256>>>(t1, qkv_w, qkv_b, qkv, NPIX, 768, CCH, 0);
    // 3. local attention (tiled)
    attn_kernel<<<dim3(7, 7, 8), 256>>>();
    // 4. proj
    gemm_nt<<<dim3(CCH/64, NPIX/64), 256>>>(ao, proj_w, proj_b, pr, NPIX, CCH, CCH, 0);
    // 5. x1 = x + pr ; t2 = LN(x1)
    ln_kernel<true><<<NPIX/32, 256>>>(x, norm2_w, norm2_b, t2);
    // 6. fc1 + GELU
    gemm_nt<<<dim3(HID/64, NPIX/64), 256>>>(t2, fc1_w, fc1_b, hbuf, NPIX, HID, CCH, 1);
    // 7. fc2
    gemm_nt<<<dim3(CCH/64, NPIX/64), 256>>>(hbuf, fc2_w, fc2_b, f2, NPIX, CCH, HID, 0);
    // 8. out
    add_t_kernel<<<dim3(NPIX/32, CCH/32), dim3(32, 8)>>>(out);
}

// round 7
// speedup vs baseline: 3.9001x; 2.0814x over previous
#include <cuda_runtime.h>
#include <math.h>
#include <stdint.h>

#define NPIX 3136   // 56*56
#define MPAD 3200   // 25 * 128 (GEMM M padding; pads are zero-init .bss)
#define CCH  256
#define HID  1024

// ---------------- scratch (allocation-free: __device__ globals) ----------------
__device__ float g_t1 [MPAD*CCH];
__device__ float g_qkv[MPAD*768];
__device__ float g_ao [MPAD*CCH];
__device__ float g_pr [MPAD*CCH];
__device__ float g_x1 [MPAD*CCH];
__device__ float g_t2 [MPAD*CCH];
__device__ float g_h  [MPAD*HID];
__device__ float g_f2 [MPAD*CCH];

__device__ __forceinline__ uint32_t f2tf32(float f) {
    uint32_t r; asm("cvt.rna.tf32.f32 %0, %1;" : "=r"(r) : "f"(f)); return r;
}

// ---------------- tf32 mma.sync GEMM: C[m,n] = act( sum_k A[m,k]*B[n,k] + bias[n] ) ----------------
// Block tile 128(M) x 64(N), 256 threads (8 warps = 4M x 2N), warp tile 32x32.
// K chunks of 32; smem rows padded to 36 floats (conflict-free fragment LDS).
// smem: As[2][128][36] | Bs[2][64][36]  = (2*4608 + 2*2304)*4 = 55296 B (dynamic)
#define GEMM_SMEM 55296
template<int ACT>
__global__ void __launch_bounds__(256) gemm_mma(const float* __restrict__ A,
                                                const float* __restrict__ B,
                                                const float* __restrict__ bias,
                                                float* __restrict__ C, int N, int K)
{
    extern __shared__ float sm[];
    const int tid = threadIdx.x;
    const int wid = tid >> 5, lane = tid & 31;
    const int grp = lane >> 2, qid = lane & 3;
    const int wm = wid & 3, wn = wid >> 2;          // warp coords: 4 x 2
    const int bm = blockIdx.y * 128, bn = blockIdx.x * 64;

    float acc[2][4][4];
    #pragma unroll
    for (int mt = 0; mt < 2; mt++)
        #pragma unroll
        for (int nt = 0; nt < 4; nt++)
            #pragma unroll
            for (int r = 0; r < 4; r++) acc[mt][nt][r] = 0.f;

    const int S = K >> 5;
    float4 pa[4], pb[2];

    // prefetch chunk 0
    #pragma unroll
    for (int it = 0; it < 4; it++) {
        const int id = tid + it*256, r = id >> 3, c4 = id & 7;
        pa[it] = *(const float4*)&A[(size_t)(bm + r)*K + c4*4];
    }
    #pragma unroll
    for (int it = 0; it < 2; it++) {
        const int id = tid + it*256, r = id >> 3, c4 = id & 7;
        pb[it] = *(const float4*)&B[(size_t)(bn + r)*K + c4*4];
    }

    for (int i = 0; i < S; i++) {
        float* As = sm + (i & 1)*4608;
        float* Bs = sm + 9216 + (i & 1)*2304;
        // stage current chunk (tf32-rna converted)
        #pragma unroll
        for (int it = 0; it < 4; it++) {
            const int id = tid + it*256, r = id >> 3, c4 = id & 7;
            uint32_t* d = (uint32_t*)&As[r*36 + c4*4];
            asm volatile("st.shared.v4.b32 [%0], {%1,%2,%3,%4};" :: "l"(d),
                "r"(f2tf32(pa[it].x)), "r"(f2tf32(pa[it].y)),
                "r"(f2tf32(pa[it].z)), "r"(f2tf32(pa[it].w)));
        }
        #pragma unroll
        for (int it = 0; it < 2; it++) {
            const int id = tid + it*256, r = id >> 3, c4 = id & 7;
            uint32_t* d = (uint32_t*)&Bs[r*36 + c4*4];
            asm volatile("st.shared.v4.b32 [%0], {%1,%2,%3,%4};" :: "l"(d),
                "r"(f2tf32(pb[it].x)), "r"(f2tf32(pb[it].y)),
                "r"(f2tf32(pb[it].z)), "r"(f2tf32(pb[it].w)));
        }
        // prefetch next chunk
        if (i + 1 < S) {
            const int kc = (i + 1) * 32;
            #pragma unroll
            for (int it = 0; it < 4; it++) {
                const int id = tid + it*256, r = id >> 3, c4 = id & 7;
                pa[it] = *(const float4*)&A[(size_t)(bm + r)*K + kc + c4*4];
            }
            #pragma unroll
            for (int it = 0; it < 2; it++) {
                const int id = tid + it*256, r = id >> 3, c4 = id & 7;
                pb[it] = *(const float4*)&B[(size_t)(bn + r)*K + kc + c4*4];
            }
        }
        __syncthreads();

        const uint32_t* Au = (const uint32_t*)As;
        const uint32_t* Bu = (const uint32_t*)Bs;
        #pragma unroll
        for (int kt = 0; kt < 4; kt++) {
            uint32_t a[2][4], b[4][2];
            #pragma unroll
            for (int mt = 0; mt < 2; mt++) {
                const int r0 = wm*32 + mt*16 + grp;
                const int c0 = kt*8 + qid;
                a[mt][0] = Au[ r0    *36 + c0    ];
                a[mt][1] = Au[(r0+8) *36 + c0    ];
                a[mt][2] = Au[ r0    *36 + c0 + 4];
                a[mt][3] = Au[(r0+8) *36 + c0 + 4];
            }
            #pragma unroll
            for (int nt = 0; nt < 4; nt++) {
                const int n0 = wn*32 + nt*8 + grp;
                const int k0 = kt*8 + qid;
                b[nt][0] = Bu[n0*36 + k0    ];
                b[nt][1] = Bu[n0*36 + k0 + 4];
            }
            #pragma unroll
            for (int mt = 0; mt < 2; mt++)
                #pragma unroll
                for (int nt = 0; nt < 4; nt++)
                    asm volatile(
                        "mma.sync.aligned.m16n8k8.row.col.f32.tf32.tf32.f32 "
                        "{%0,%1,%2,%3}, {%4,%5,%6,%7}, {%8,%9}, {%0,%1,%2,%3};"
                        : "+f"(acc[mt][nt][0]), "+f"(acc[mt][nt][1]),
                          "+f"(acc[mt][nt][2]), "+f"(acc[mt][nt][3])
                        : "r"(a[mt][0]), "r"(a[mt][1]), "r"(a[mt][2]), "r"(a[mt][3]),
                          "r"(b[nt][0]), "r"(b[nt][1]));
        }
        __syncthreads();
    }

    // epilogue: bias + optional exact GELU, float2 stores
    #pragma unroll
    for (int mt = 0; mt < 2; mt++) {
        #pragma unroll
        for (int nt = 0; nt < 4; nt++) {
            const int row0 = bm + wm*32 + mt*16 + grp;
            const int col  = bn + wn*32 + nt*8 + qid*2;
            const float b0 = bias[col], b1 = bias[col+1];
            float v0 = acc[mt][nt][0] + b0;
            float v1 = acc[mt][nt][1] + b1;
            float v2 = acc[mt][nt][2] + b0;
            float v3 = acc[mt][nt][3] + b1;
            if (ACT == 1) {
                v0 = 0.5f*v0*(1.f + erff(v0*0.70710678118654752f));
                v1 = 0.5f*v1*(1.f + erff(v1*0.70710678118654752f));
                v2 = 0.5f*v2*(1.f + erff(v2*0.70710678118654752f));
                v3 = 0.5f*v3*(1.f + erff(v3*0.70710678118654752f));
            }
            *(float2*)&C[(size_t)row0*N + col]     = make_float2(v0, v1);
            *(float2*)&C[(size_t)(row0+8)*N + col] = make_float2(v2, v3);
        }
    }
}

// ---------------- channel LayerNorm (+optional residual add) ----------------
template <bool ADD>
__global__ void ln_kernel(const float* __restrict__ x,
                          const float* __restrict__ w, const float* __restrict__ b,
                          float* __restrict__ t)
{
    __shared__ float s[CCH][33];
    __shared__ float rsum[8][32], rsum2[8][32];
    __shared__ float mu_s[32], rs_s[32];
    const int tid  = threadIdx.x;
    const int lane = tid & 31, wp = tid >> 5;
    const int p0   = blockIdx.x * 32;

    if (ADD) {
        const int cl = tid & 31, pl8 = tid >> 5;
        #pragma unroll
        for (int pp = 0; pp < 4; pp++) {
            const int pl = pp*8 + pl8;
            #pragma unroll
            for (int cc = 0; cc < 8; cc++) {
                const int c = cc*32 + cl;
                s[c][pl] = g_pr[(p0+pl)*CCH + c];
            }
        }
        __syncthreads();
    }
    float sum = 0.f, sum2 = 0.f;
    #pragma unroll
    for (int k = 0; k < 32; k++) {
        const int c = wp*32 + k;
        float v = x[c*NPIX + p0 + lane];
        if (ADD) v += s[c][lane];
        s[c][lane] = v;
        sum += v; sum2 += v*v;
    }
    rsum[wp][lane] = sum; rsum2[wp][lane] = sum2;
    __syncthreads();
    if (tid < 32) {
        float a = 0.f, a2 = 0.f;
        #pragma unroll
        for (int k = 0; k < 8; k++) { a += rsum[k][tid]; a2 += rsum2[k][tid]; }
        const float mu  = a * (1.f/CCH);
        const float var = a2 * (1.f/CCH) - mu*mu;
        mu_s[tid] = mu; rs_s[tid] = rsqrtf(var + 1e-5f);
    }
    __syncthreads();
    {
        const int cl = tid & 31, pl8 = tid >> 5;
        #pragma unroll
        for (int pp = 0; pp < 4; pp++) {
            const int pl = pp*8 + pl8;
            const float mu = mu_s[pl], rs = rs_s[pl];
            #pragma unroll
            for (int cc = 0; cc < 8; cc++) {
                const int c = cc*32 + cl;
                const float y = s[c][pl];
                if (ADD) g_x1[(p0+pl)*CCH + c] = y;
                t[(p0+pl)*CCH + c] = (y - mu)*rs*w[c] + b[c];
            }
        }
    }
}

// ---------------- local window attention (tiled smem, known-good) ----------------
__global__ void attn_kernel()
{
    __shared__ float Ks[196][36];
    __shared__ float Vs[196][36];
    __shared__ float Ps[64][56];
    const int tid = threadIdx.x;
    const int h  = blockIdx.z;
    const int ti = blockIdx.y, tj = blockIdx.x;
    const int gi0 = ti*8 - 3, gj0 = tj*8 - 3;

    for (int idx = tid; idx < 196*32; idx += 256) {
        const int pix = idx >> 5, d = idx & 31;
        const int pi = pix / 14, pj = pix - pi*14;
        const int ai = gi0 + pi, aj = gj0 + pj;
        float kv = 0.f, vv = 0.f;
        if (ai >= 0 && ai < 56 && aj >= 0 && aj < 56) {
            const int m = ai*56 + aj;
            kv = g_qkv[m*768 + 256 + h*32 + d];
            vv = g_qkv[m*768 + 512 + h*32 + d];
        }
        Ks[pix][d] = kv;
        Vs[pix][d] = vv;
    }
    __syncthreads();

    const int q  = tid >> 2, qu = tid & 3;
    const int qi = q >> 3,  qj = q & 7;
    const int gqi = ti*8 + qi, gqj = tj*8 + qj;
    const int n = gqi*56 + gqj;

    float qv[32];
    {
        const float4* qp = (const float4*)&g_qkv[n*768 + h*32];
        #pragma unroll
        for (int k = 0; k < 8; k++) {
            const float4 v = qp[k];
            qv[4*k+0] = v.x; qv[4*k+1] = v.y; qv[4*k+2] = v.z; qv[4*k+3] = v.w;
        }
    }

    float sc[13];
    #pragma unroll
    for (int j = 0; j < 13; j++) sc[j] = -3.0e38f;
    #pragma unroll
    for (int j = 0; j < 13; j++) {
        const int s = qu + 4*j;
        if (s < 49) {
            const int dy = s / 7 - 3, dx = s - (s/7)*7 - 3;
            const int ai = gqi + dy, aj = gqj + dx;
            if (ai >= 0 && ai < 56 && aj >= 0 && aj < 56) {
                const int nb = (qi + dy + 3)*14 + (qj + dx + 3);
                const float4* kp = (const float4*)&Ks[nb][0];
                float acc = 0.f;
                #pragma unroll
                for (int k = 0; k < 8; k++) {
                    const float4 kv = kp[k];
                    acc += qv[4*k+0]*kv.x + qv[4*k+1]*kv.y
                         + qv[4*k+2]*kv.z + qv[4*k+3]*kv.w;
                }
                sc[j] = acc * 0.17677669529663687f;
            }
        }
    }

    const unsigned FULL = 0xffffffffu;
    float mx = sc[0];
    #pragma unroll
    for (int j = 1; j < 13; j++) mx = fmaxf(mx, sc[j]);
    mx = fmaxf(mx, __shfl_xor_sync(FULL, mx, 1));
    mx = fmaxf(mx, __shfl_xor_sync(FULL, mx, 2));
    float lsum = 0.f;
    float pe[13];
    #pragma unroll
    for (int j = 0; j < 13; j++) { pe[j] = __expf(sc[j] - mx); lsum += pe[j]; }
    lsum += __shfl_xor_sync(FULL, lsum, 1);
    lsum += __shfl_xor_sync(FULL, lsum, 2);
    const float inv = 1.f / lsum;
    #pragma unroll
    for (int j = 0; j < 13; j++) {
        const int s = qu + 4*j;
        if (s < 49) Ps[q][s] = pe[j] * inv;
    }
    __syncthreads();

    const int d0 = qu*8;
    float acc[8] = {};
    #pragma unroll
    for (int dy = -3; dy <= 3; dy++) {
        const int rowbase = (qi + dy + 3)*14 + (qj + 3);
        const int sbase = (dy+3)*7;
        #pragma unroll
        for (int dx = -3; dx <= 3; dx++) {
            const float p = Ps[q][sbase + dx + 3];
            const float4* vp = (const float4*)&Vs[rowbase + dx][d0];
            const float4 v0 = vp[0], v1 = vp[1];
            acc[0] += p*v0.x; acc[1] += p*v0.y; acc[2] += p*v0.z; acc[3] += p*v0.w;
            acc[4] += p*v1.x; acc[5] += p*v1.y; acc[6] += p*v1.z; acc[7] += p*v1.w;
        }
    }
    float4* op = (float4*)&g_ao[n*CCH + h*32 + d0];
    op[0] = make_float4(acc[0], acc[1], acc[2], acc[3]);
    op[1] = make_float4(acc[4], acc[5], acc[6], acc[7]);
}

// ---------------- final: out[c, n] = g_x1[n,c] + g_f2[n,c] ----------------
__global__ void add_t_kernel(float* __restrict__ out)
{
    __shared__ float s[32][33];
    const int tx = threadIdx.x, ty = threadIdx.y;
    const int n0 = blockIdx.x * 32, c0 = blockIdx.y * 32;
    #pragma unroll
    for (int r = 0; r < 4; r++) {
        const int nl = ty + 8*r;
        const int idx = (n0+nl)*CCH + c0 + tx;
        s[tx][nl] = g_x1[idx] + g_f2[idx];
    }
    __syncthreads();
    #pragma unroll
    for (int r = 0; r < 4; r++) {
        const int cl = ty + 8*r;
        out[(c0+cl)*NPIX + n0 + tx] = s[cl][tx];
    }
}

extern "C" void kernel_launch(void* const* d_in, const int* in_sizes, int n_in,
                              void* d_out, int out_size)
{
    const float* x       = (const float*)d_in[0];
    const float* norm1_w = (const float*)d_in[1];
    const float* norm1_b = (const float*)d_in[2];
    const float* qkv_w   = (const float*)d_in[3];
    const float* qkv_b   = (const float*)d_in[4];
    const float* proj_w  = (const float*)d_in[5];
    const float* proj_b  = (const float*)d_in[6];
    const float* norm2_w = (const float*)d_in[7];
    const float* norm2_b = (const float*)d_in[8];
    const float* fc1_w   = (const float*)d_in[9];
    const float* fc1_b   = (const float*)d_in[10];
    const float* fc2_w   = (const float*)d_in[11];
    const float* fc2_b   = (const float*)d_in[12];
    float* out = (float*)d_out;

    static float *t1 = nullptr, *qkv = nullptr, *t2 = nullptr, *hbuf = nullptr,
                 *f2 = nullptr, *ao = nullptr, *pr = nullptr;
    if (!t1) {
        cudaGetSymbolAddress((void**)&t1,   g_t1);
        cudaGetSymbolAddress((void**)&qkv,  g_qkv);
        cudaGetSymbolAddress((void**)&ao,   g_ao);
        cudaGetSymbolAddress((void**)&t2,   g_t2);
        cudaGetSymbolAddress((void**)&hbuf, g_h);
        cudaGetSymbolAddress((void**)&f2,   g_f2);
        cudaGetSymbolAddress((void**)&pr,   g_pr);
        cudaFuncSetAttribute(gemm_mma<0>, cudaFuncAttributeMaxDynamicSharedMemorySize, GEMM_SMEM);
        cudaFuncSetAttribute(gemm_mma<1>, cudaFuncAttributeMaxDynamicSharedMemorySize, GEMM_SMEM);
    }

    // 1. LN1
    ln_kernel<false><<<NPIX/32, 256>>>(x, norm1_w, norm1_b, t1);
    // 2. QKV: [3200,768]
    gemm_mma<0><<<dim3(768/64, MPAD/128), 256, GEMM_SMEM>>>(t1, qkv_w, qkv_b, qkv, 768, CCH);
    // 3. local attention
    attn_kernel<<<dim3(7, 7, 8), 256>>>();
    // 4. proj
    gemm_mma<0><<<dim3(CCH/64, MPAD/128), 256, GEMM_SMEM>>>(ao, proj_w, proj_b, pr, CCH, CCH);
    // 5. x1 = x + pr ; t2 = LN(x1)
    ln_kernel<true><<<NPIX/32, 256>>>(x, norm2_w, norm2_b, t2);
    // 6. fc1 + GELU
    gemm_mma<1><<<dim3(HID/64, MPAD/128), 256, GEMM_SMEM>>>(t2, fc1_w, fc1_b, hbuf, HID, CCH);
    // 7. fc2
    gemm_mma<0><<<dim3(CCH/64, MPAD/128), 256, GEMM_SMEM>>>(hbuf, fc2_w, fc2_b, f2, CCH, HID);
    // 8. out
    add_t_kernel<<<dim3(NPIX/32, CCH/32), dim3(32, 8)>>>(out);
}

// round 8
// speedup vs baseline: 4.2445x; 1.0883x over previous
#include <cuda_runtime.h>
#include <math.h>
#include <stdint.h>

#define NPIX 3136   // 56*56 = 49 * 64 (exact M tiling, no padding)
#define CCH  256
#define HID  1024

// ---------------- scratch (allocation-free: __device__ globals) ----------------
__device__ float g_t1 [NPIX*CCH];
__device__ float g_qkv[NPIX*768];
__device__ float g_ao [NPIX*CCH];
__device__ float g_pr [NPIX*CCH];
__device__ float g_x1 [NPIX*CCH];
__device__ float g_t2 [NPIX*CCH];
__device__ float g_h  [NPIX*HID];
__device__ float g_f2 [NPIX*CCH];

__device__ __forceinline__ uint32_t f2tf32(float f) {
    uint32_t r; asm("cvt.rna.tf32.f32 %0, %1;" : "=r"(r) : "f"(f)); return r;
}

// ---------------- tf32 mma.sync GEMM: C[m,n] = act( sum_k A[m,k]*B[n,k] + bias[n] ) ----------------
// Block tile 64(M) x 64(N), 128 threads (4 warps = 2M x 2N), warp tile 32x32.
// K chunks of 32; smem rows padded to 36 floats (conflict-free fragment LDS).
// smem: As[2][64][36] | Bs[2][64][36] = 9216 floats = 36864 B (dynamic)
#define GEMM_SMEM 36864
template<int ACT>
__global__ void __launch_bounds__(128) gemm_mma(const float* __restrict__ A,
                                                const float* __restrict__ B,
                                                const float* __restrict__ bias,
                                                float* __restrict__ C, int N, int K)
{
    extern __shared__ float sm[];
    const int tid = threadIdx.x;
    const int wid = tid >> 5, lane = tid & 31;
    const int grp = lane >> 2, qid = lane & 3;
    const int wm = wid & 1, wn = wid >> 1;          // warp coords: 2 x 2
    const int bm = blockIdx.y * 64, bn = blockIdx.x * 64;

    float acc[2][4][4];
    #pragma unroll
    for (int mt = 0; mt < 2; mt++)
        #pragma unroll
        for (int nt = 0; nt < 4; nt++)
            #pragma unroll
            for (int r = 0; r < 4; r++) acc[mt][nt][r] = 0.f;

    const int S = K >> 5;
    float4 pa[4], pb[4];

    // prefetch chunk 0 (64 rows x 32 cols each of A,B; 4 float4/thread each)
    #pragma unroll
    for (int it = 0; it < 4; it++) {
        const int id = tid + it*128, r = id >> 3, c4 = id & 7;
        pa[it] = *(const float4*)&A[(size_t)(bm + r)*K + c4*4];
        pb[it] = *(const float4*)&B[(size_t)(bn + r)*K + c4*4];
    }

    for (int i = 0; i < S; i++) {
        float* As = sm + (i & 1)*2304;
        float* Bs = sm + 4608 + (i & 1)*2304;
        // stage current chunk (tf32-rna converted)
        #pragma unroll
        for (int it = 0; it < 4; it++) {
            const int id = tid + it*128, r = id >> 3, c4 = id & 7;
            uint32_t* da = (uint32_t*)&As[r*36 + c4*4];
            uint32_t* db = (uint32_t*)&Bs[r*36 + c4*4];
            asm volatile("st.shared.v4.b32 [%0], {%1,%2,%3,%4};" :: "l"(da),
                "r"(f2tf32(pa[it].x)), "r"(f2tf32(pa[it].y)),
                "r"(f2tf32(pa[it].z)), "r"(f2tf32(pa[it].w)));
            asm volatile("st.shared.v4.b32 [%0], {%1,%2,%3,%4};" :: "l"(db),
                "r"(f2tf32(pb[it].x)), "r"(f2tf32(pb[it].y)),
                "r"(f2tf32(pb[it].z)), "r"(f2tf32(pb[it].w)));
        }
        // prefetch next chunk
        if (i + 1 < S) {
            const int kc = (i + 1) * 32;
            #pragma unroll
            for (int it = 0; it < 4; it++) {
                const int id = tid + it*128, r = id >> 3, c4 = id & 7;
                pa[it] = *(const float4*)&A[(size_t)(bm + r)*K + kc + c4*4];
                pb[it] = *(const float4*)&B[(size_t)(bn + r)*K + kc + c4*4];
            }
        }
        __syncthreads();

        const uint32_t* Au = (const uint32_t*)As;
        const uint32_t* Bu = (const uint32_t*)Bs;
        #pragma unroll
        for (int kt = 0; kt < 4; kt++) {
            uint32_t a[2][4], b[4][2];
            #pragma unroll
            for (int mt = 0; mt < 2; mt++) {
                const int r0 = wm*32 + mt*16 + grp;
                const int c0 = kt*8 + qid;
                a[mt][0] = Au[ r0    *36 + c0    ];
                a[mt][1] = Au[(r0+8) *36 + c0    ];
                a[mt][2] = Au[ r0    *36 + c0 + 4];
                a[mt][3] = Au[(r0+8) *36 + c0 + 4];
            }
            #pragma unroll
            for (int nt = 0; nt < 4; nt++) {
                const int n0 = wn*32 + nt*8 + grp;
                const int k0 = kt*8 + qid;
                b[nt][0] = Bu[n0*36 + k0    ];
                b[nt][1] = Bu[n0*36 + k0 + 4];
            }
            #pragma unroll
            for (int mt = 0; mt < 2; mt++)
                #pragma unroll
                for (int nt = 0; nt < 4; nt++)
                    asm volatile(
                        "mma.sync.aligned.m16n8k8.row.col.f32.tf32.tf32.f32 "
                        "{%0,%1,%2,%3}, {%4,%5,%6,%7}, {%8,%9}, {%0,%1,%2,%3};"
                        : "+f"(acc[mt][nt][0]), "+f"(acc[mt][nt][1]),
                          "+f"(acc[mt][nt][2]), "+f"(acc[mt][nt][3])
                        : "r"(a[mt][0]), "r"(a[mt][1]), "r"(a[mt][2]), "r"(a[mt][3]),
                          "r"(b[nt][0]), "r"(b[nt][1]));
        }
        __syncthreads();
    }

    // epilogue: bias + optional exact GELU, float2 stores
    #pragma unroll
    for (int mt = 0; mt < 2; mt++) {
        #pragma unroll
        for (int nt = 0; nt < 4; nt++) {
            const int row0 = bm + wm*32 + mt*16 + grp;
            const int col  = bn + wn*32 + nt*8 + qid*2;
            const float b0 = bias[col], b1 = bias[col+1];
            float v0 = acc[mt][nt][0] + b0;
            float v1 = acc[mt][nt][1] + b1;
            float v2 = acc[mt][nt][2] + b0;
            float v3 = acc[mt][nt][3] + b1;
            if (ACT == 1) {
                v0 = 0.5f*v0*(1.f + erff(v0*0.70710678118654752f));
                v1 = 0.5f*v1*(1.f + erff(v1*0.70710678118654752f));
                v2 = 0.5f*v2*(1.f + erff(v2*0.70710678118654752f));
                v3 = 0.5f*v3*(1.f + erff(v3*0.70710678118654752f));
            }
            *(float2*)&C[(size_t)row0*N + col]     = make_float2(v0, v1);
            *(float2*)&C[(size_t)(row0+8)*N + col] = make_float2(v2, v3);
        }
    }
}

// ---------------- channel LayerNorm (+optional residual add) ----------------
template <bool ADD>
__global__ void ln_kernel(const float* __restrict__ x,
                          const float* __restrict__ w, const float* __restrict__ b,
                          float* __restrict__ t)
{
    __shared__ float s[CCH][33];
    __shared__ float rsum[8][32], rsum2[8][32];
    __shared__ float mu_s[32], rs_s[32];
    const int tid  = threadIdx.x;
    const int lane = tid & 31, wp = tid >> 5;
    const int p0   = blockIdx.x * 32;

    if (ADD) {
        const int cl = tid & 31, pl8 = tid >> 5;
        #pragma unroll
        for (int pp = 0; pp < 4; pp++) {
            const int pl = pp*8 + pl8;
            #pragma unroll
            for (int cc = 0; cc < 8; cc++) {
                const int c = cc*32 + cl;
                s[c][pl] = g_pr[(p0+pl)*CCH + c];
            }
        }
        __syncthreads();
    }
    float sum = 0.f, sum2 = 0.f;
    #pragma unroll
    for (int k = 0; k < 32; k++) {
        const int c = wp*32 + k;
        float v = x[c*NPIX + p0 + lane];
        if (ADD) v += s[c][lane];
        s[c][lane] = v;
        sum += v; sum2 += v*v;
    }
    rsum[wp][lane] = sum; rsum2[wp][lane] = sum2;
    __syncthreads();
    if (tid < 32) {
        float a = 0.f, a2 = 0.f;
        #pragma unroll
        for (int k = 0; k < 8; k++) { a += rsum[k][tid]; a2 += rsum2[k][tid]; }
        const float mu  = a * (1.f/CCH);
        const float var = a2 * (1.f/CCH) - mu*mu;
        mu_s[tid] = mu; rs_s[tid] = rsqrtf(var + 1e-5f);
    }
    __syncthreads();
    {
        const int cl = tid & 31, pl8 = tid >> 5;
        #pragma unroll
        for (int pp = 0; pp < 4; pp++) {
            const int pl = pp*8 + pl8;
            const float mu = mu_s[pl], rs = rs_s[pl];
            #pragma unroll
            for (int cc = 0; cc < 8; cc++) {
                const int c = cc*32 + cl;
                const float y = s[c][pl];
                if (ADD) g_x1[(p0+pl)*CCH + c] = y;
                t[(p0+pl)*CCH + c] = (y - mu)*rs*w[c] + b[c];
            }
        }
    }
}

// ---------------- local window attention (tiled smem, known-good) ----------------
__global__ void attn_kernel()
{
    __shared__ float Ks[196][36];
    __shared__ float Vs[196][36];
    __shared__ float Ps[64][56];
    const int tid = threadIdx.x;
    const int h  = blockIdx.z;
    const int ti = blockIdx.y, tj = blockIdx.x;
    const int gi0 = ti*8 - 3, gj0 = tj*8 - 3;

    for (int idx = tid; idx < 196*32; idx += 256) {
        const int pix = idx >> 5, d = idx & 31;
        const int pi = pix / 14, pj = pix - pi*14;
        const int ai = gi0 + pi, aj = gj0 + pj;
        float kv = 0.f, vv = 0.f;
        if (ai >= 0 && ai < 56 && aj >= 0 && aj < 56) {
            const int m = ai*56 + aj;
            kv = g_qkv[m*768 + 256 + h*32 + d];
            vv = g_qkv[m*768 + 512 + h*32 + d];
        }
        Ks[pix][d] = kv;
        Vs[pix][d] = vv;
    }
    __syncthreads();

    const int q  = tid >> 2, qu = tid & 3;
    const int qi = q >> 3,  qj = q & 7;
    const int gqi = ti*8 + qi, gqj = tj*8 + qj;
    const int n = gqi*56 + gqj;

    float qv[32];
    {
        const float4* qp = (const float4*)&g_qkv[n*768 + h*32];
        #pragma unroll
        for (int k = 0; k < 8; k++) {
            const float4 v = qp[k];
            qv[4*k+0] = v.x; qv[4*k+1] = v.y; qv[4*k+2] = v.z; qv[4*k+3] = v.w;
        }
    }

    float sc[13];
    #pragma unroll
    for (int j = 0; j < 13; j++) sc[j] = -3.0e38f;
    #pragma unroll
    for (int j = 0; j < 13; j++) {
        const int s = qu + 4*j;
        if (s < 49) {
            const int dy = s / 7 - 3, dx = s - (s/7)*7 - 3;
            const int ai = gqi + dy, aj = gqj + dx;
            if (ai >= 0 && ai < 56 && aj >= 0 && aj < 56) {
                const int nb = (qi + dy + 3)*14 + (qj + dx + 3);
                const float4* kp = (const float4*)&Ks[nb][0];
                float acc = 0.f;
                #pragma unroll
                for (int k = 0; k < 8; k++) {
                    const float4 kv = kp[k];
                    acc += qv[4*k+0]*kv.x + qv[4*k+1]*kv.y
                         + qv[4*k+2]*kv.z + qv[4*k+3]*kv.w;
                }
                sc[j] = acc * 0.17677669529663687f;
            }
        }
    }

    const unsigned FULL = 0xffffffffu;
    float mx = sc[0];
    #pragma unroll
    for (int j = 1; j < 13; j++) mx = fmaxf(mx, sc[j]);
    mx = fmaxf(mx, __shfl_xor_sync(FULL, mx, 1));
    mx = fmaxf(mx, __shfl_xor_sync(FULL, mx, 2));
    float lsum = 0.f;
    float pe[13];
    #pragma unroll
    for (int j = 0; j < 13; j++) { pe[j] = __expf(sc[j] - mx); lsum += pe[j]; }
    lsum += __shfl_xor_sync(FULL, lsum, 1);
    lsum += __shfl_xor_sync(FULL, lsum, 2);
    const float inv = 1.f / lsum;
    #pragma unroll
    for (int j = 0; j < 13; j++) {
        const int s = qu + 4*j;
        if (s < 49) Ps[q][s] = pe[j] * inv;
    }
    __syncthreads();

    const int d0 = qu*8;
    float acc[8] = {};
    #pragma unroll
    for (int dy = -3; dy <= 3; dy++) {
        const int rowbase = (qi + dy + 3)*14 + (qj + 3);
        const int sbase = (dy+3)*7;
        #pragma unroll
        for (int dx = -3; dx <= 3; dx++) {
            const float p = Ps[q][sbase + dx + 3];
            const float4* vp = (const float4*)&Vs[rowbase + dx][d0];
            const float4 v0 = vp[0], v1 = vp[1];
            acc[0] += p*v0.x; acc[1] += p*v0.y; acc[2] += p*v0.z; acc[3] += p*v0.w;
            acc[4] += p*v1.x; acc[5] += p*v1.y; acc[6] += p*v1.z; acc[7] += p*v1.w;
        }
    }
    float4* op = (float4*)&g_ao[n*CCH + h*32 + d0];
    op[0] = make_float4(acc[0], acc[1], acc[2], acc[3]);
    op[1] = make_float4(acc[4], acc[5], acc[6], acc[7]);
}

// ---------------- final: out[c, n] = g_x1[n,c] + g_f2[n,c] ----------------
__global__ void add_t_kernel(float* __restrict__ out)
{
    __shared__ float s[32][33];
    const int tx = threadIdx.x, ty = threadIdx.y;
    const int n0 = blockIdx.x * 32, c0 = blockIdx.y * 32;
    #pragma unroll
    for (int r = 0; r < 4; r++) {
        const int nl = ty + 8*r;
        const int idx = (n0+nl)*CCH + c0 + tx;
        s[tx][nl] = g_x1[idx] + g_f2[idx];
    }
    __syncthreads();
    #pragma unroll
    for (int r = 0; r < 4; r++) {
        const int cl = ty + 8*r;
        out[(c0+cl)*NPIX + n0 + tx] = s[cl][tx];
    }
}

extern "C" void kernel_launch(void* const* d_in, const int* in_sizes, int n_in,
                              void* d_out, int out_size)
{
    const float* x       = (const float*)d_in[0];
    const float* norm1_w = (const float*)d_in[1];
    const float* norm1_b = (const float*)d_in[2];
    const float* qkv_w   = (const float*)d_in[3];
    const float* qkv_b   = (const float*)d_in[4];
    const float* proj_w  = (const float*)d_in[5];
    const float* proj_b  = (const float*)d_in[6];
    const float* norm2_w = (const float*)d_in[7];
    const float* norm2_b = (const float*)d_in[8];
    const float* fc1_w   = (const float*)d_in[9];
    const float* fc1_b   = (const float*)d_in[10];
    const float* fc2_w   = (const float*)d_in[11];
    const float* fc2_b   = (const float*)d_in[12];
    float* out = (float*)d_out;

    static float *t1 = nullptr, *qkv = nullptr, *t2 = nullptr, *hbuf = nullptr,
                 *f2 = nullptr, *ao = nullptr, *pr = nullptr;
    if (!t1) {
        cudaGetSymbolAddress((void**)&t1,   g_t1);
        cudaGetSymbolAddress((void**)&qkv,  g_qkv);
        cudaGetSymbolAddress((void**)&ao,   g_ao);
        cudaGetSymbolAddress((void**)&t2,   g_t2);
        cudaGetSymbolAddress((void**)&hbuf, g_h);
        cudaGetSymbolAddress((void**)&f2,   g_f2);
        cudaGetSymbolAddress((void**)&pr,   g_pr);
        cudaFuncSetAttribute(gemm_mma<0>, cudaFuncAttributeMaxDynamicSharedMemorySize, GEMM_SMEM);
        cudaFuncSetAttribute(gemm_mma<1>, cudaFuncAttributeMaxDynamicSharedMemorySize, GEMM_SMEM);
    }

    // 1. LN1
    ln_kernel<false><<<NPIX/32, 256>>>(x, norm1_w, norm1_b, t1);
    // 2. QKV: [3136,768]
    gemm_mma<0><<<dim3(768/64, NPIX/64), 128, GEMM_SMEM>>>(t1, qkv_w, qkv_b, qkv, 768, CCH);
    // 3. local attention
    attn_kernel<<<dim3(7, 7, 8), 256>>>();
    // 4. proj
    gemm_mma<0><<<dim3(CCH/64, NPIX/64), 128, GEMM_SMEM>>>(ao, proj_w, proj_b, pr, CCH, CCH);
    // 5. x1 = x + pr ; t2 = LN(x1)
    ln_kernel<true><<<NPIX/32, 256>>>(x, norm2_w, norm2_b, t2);
    // 6. fc1 + GELU
    gemm_mma<1><<<dim3(HID/64, NPIX/64), 128, GEMM_SMEM>>>(t2, fc1_w, fc1_b, hbuf, HID, CCH);
    // 7. fc2
    gemm_mma<0><<<dim3(CCH/64, NPIX/64), 128, GEMM_SMEM>>>(hbuf, fc2_w, fc2_b, f2, CCH, HID);
    // 8. out
    add_t_kernel<<<dim3(NPIX/32, CCH/32), dim3(32, 8)>>>(out);
}